// round 17
// baseline (speedup 1.0000x reference)
#include <cuda_runtime.h>
#include <math.h>
#include <stdint.h>

#define NB 32
#define NC 256
#define NH 64
#define NW 64
#define MIP 8
#define EPS 1e-5f
#define SPC 4   // slices per CTA in k_reduce_strip

// Intermediates (no allocation allowed -> device globals)
__device__ __align__(16) float g_s [NB * NC * 128];   // strip-pooled+BN : 4 MB
__device__ __align__(16) float g_y [NB * MIP * 128];  // conv1+BN+hswish : 128 KB

// ---------------------------------------------------------------------------
// Kernel 1: 4 slices per CTA, 2-stage TMA pipeline. 128 threads.
// wait(stage) -> compute -> sync -> issue(next into freed stage).
// Slice order monotonic (preserves x-tail L2 state for k_apply).
// ---------------------------------------------------------------------------
__global__ __launch_bounds__(128) void k_reduce_strip(
    const float* __restrict__ x,
    const float* __restrict__ sph_w3, const float* __restrict__ sph_w7,
    const float* __restrict__ sph_g,  const float* __restrict__ sph_b,
    const float* __restrict__ sph_m,  const float* __restrict__ sph_v,
    const float* __restrict__ spw_w3, const float* __restrict__ spw_w7,
    const float* __restrict__ spw_g,  const float* __restrict__ spw_b,
    const float* __restrict__ spw_m,  const float* __restrict__ spw_v)
{
    __shared__ __align__(128) float tile[2][NH * NW];  // 2 x 16 KB
    __shared__ unsigned long long mbar[2];
    __shared__ __align__(16) float4 csum[128];         // column partials (2 KB)
    __shared__ float  mrow[NH];
    __shared__ float  mcol[NW];

    const int blk = blockIdx.x;       // 0..2047
    const int tid = threadIdx.x;      // 0..127
    const int grp = tid >> 4;         // 0..7 (row-group)
    const int w4  = tid & 15;         // float4 chunk along W

    const uint32_t mbar_a0 = (uint32_t)__cvta_generic_to_shared(&mbar[0]);
    const uint32_t mbar_a1 = (uint32_t)__cvta_generic_to_shared(&mbar[1]);
    const uint32_t tile_a0 = (uint32_t)__cvta_generic_to_shared(tile[0]);
    const uint32_t tile_a1 = (uint32_t)__cvta_generic_to_shared(tile[1]);

    const float* xbase = x + (size_t)blk * SPC * (NH * NW);

    if (tid == 0) {
        asm volatile("mbarrier.init.shared.b64 [%0], 1;" :: "r"(mbar_a0) : "memory");
        asm volatile("mbarrier.init.shared.b64 [%0], 1;" :: "r"(mbar_a1) : "memory");
    }
    __syncthreads();
    if (tid == 0) {
        // Prologue: slices 0 and 1 in flight.
        asm volatile("mbarrier.arrive.expect_tx.shared.b64 _, [%0], %1;"
                     :: "r"(mbar_a0), "r"(16384u) : "memory");
        asm volatile(
            "cp.async.bulk.shared::cta.global.mbarrier::complete_tx::bytes "
            "[%0], [%1], %2, [%3];"
            :: "r"(tile_a0), "l"(xbase), "r"(16384u), "r"(mbar_a0) : "memory");
        asm volatile("mbarrier.arrive.expect_tx.shared.b64 _, [%0], %1;"
                     :: "r"(mbar_a1), "r"(16384u) : "memory");
        asm volatile(
            "cp.async.bulk.shared::cta.global.mbarrier::complete_tx::bytes "
            "[%0], [%1], %2, [%3];"
            :: "r"(tile_a1), "l"(xbase + NH * NW), "r"(16384u), "r"(mbar_a1) : "memory");
    }

#pragma unroll
    for (int i = 0; i < SPC; i++) {
        const int      st     = i & 1;
        const uint32_t mbar_a = st ? mbar_a1 : mbar_a0;
        const uint32_t phase  = (i >> 1) & 1;
        const int      bc     = blk * SPC + i;
        const int      c      = bc & (NC - 1);

        // Wait for this stage's TMA.
        {
            uint32_t done = 0;
            while (!done) {
                asm volatile(
                    "{\n\t.reg .pred p;\n\t"
                    "mbarrier.try_wait.parity.acquire.cta.shared::cta.b64 p, [%1], %2;\n\t"
                    "selp.b32 %0, 1, 0, p;\n\t}"
                    : "=r"(done) : "r"(mbar_a), "r"(phase) : "memory");
            }
        }

        const float4* t4 = (const float4*)tile[st];
        float4 v0 = t4[tid];
        float4 v1 = t4[tid + 128];
        float4 v2 = t4[tid + 256];
        float4 v3 = t4[tid + 384];
        float4 v4 = t4[tid + 512];
        float4 v5 = t4[tid + 640];
        float4 v6 = t4[tid + 768];
        float4 v7 = t4[tid + 896];

        float4 cs;
        cs.x = (v0.x + v1.x) + (v2.x + v3.x) + ((v4.x + v5.x) + (v6.x + v7.x));
        cs.y = (v0.y + v1.y) + (v2.y + v3.y) + ((v4.y + v5.y) + (v6.y + v7.y));
        cs.z = (v0.z + v1.z) + (v2.z + v3.z) + ((v4.z + v5.z) + (v6.z + v7.z));
        cs.w = (v0.w + v1.w) + (v2.w + v3.w) + ((v4.w + v5.w) + (v6.w + v7.w));
        csum[tid] = cs;

        float r0 = v0.x + v0.y + v0.z + v0.w;
        float r1 = v1.x + v1.y + v1.z + v1.w;
        float r2 = v2.x + v2.y + v2.z + v2.w;
        float r3 = v3.x + v3.y + v3.z + v3.w;
        float r4 = v4.x + v4.y + v4.z + v4.w;
        float r5 = v5.x + v5.y + v5.z + v5.w;
        float r6 = v6.x + v6.y + v6.z + v6.w;
        float r7 = v7.x + v7.y + v7.z + v7.w;
#pragma unroll
        for (int m = 8; m >= 1; m >>= 1) {
            r0 += __shfl_xor_sync(0xffffffffu, r0, m);
            r1 += __shfl_xor_sync(0xffffffffu, r1, m);
            r2 += __shfl_xor_sync(0xffffffffu, r2, m);
            r3 += __shfl_xor_sync(0xffffffffu, r3, m);
            r4 += __shfl_xor_sync(0xffffffffu, r4, m);
            r5 += __shfl_xor_sync(0xffffffffu, r5, m);
            r6 += __shfl_xor_sync(0xffffffffu, r6, m);
            r7 += __shfl_xor_sync(0xffffffffu, r7, m);
        }
        if (w4 == 0) {
            mrow[grp]      = r0 * (1.f / 64.f);
            mrow[grp + 8]  = r1 * (1.f / 64.f);
            mrow[grp + 16] = r2 * (1.f / 64.f);
            mrow[grp + 24] = r3 * (1.f / 64.f);
            mrow[grp + 32] = r4 * (1.f / 64.f);
            mrow[grp + 40] = r5 * (1.f / 64.f);
            mrow[grp + 48] = r6 * (1.f / 64.f);
            mrow[grp + 56] = r7 * (1.f / 64.f);
        }
        __syncthreads();

        if (tid < 64) {
            const float* cf = (const float*)csum;
            float s = 0.f;
#pragma unroll
            for (int g = 0; g < 8; g++) s += cf[g * 64 + tid];
            mcol[tid] = s * (1.f / 64.f);
        }
        __syncthreads();

        {
            const int l = tid & 63;
            const float* src; const float* w3; const float* w7;
            float g, bb, mm, vv; int off;
            if (tid < 64) {
                src = mrow; w3 = sph_w3 + c * 3; w7 = sph_w7 + c * 7;
                g = sph_g[c]; bb = sph_b[c]; mm = sph_m[c]; vv = sph_v[c]; off = 0;
            } else {
                src = mcol; w3 = spw_w3 + c * 3; w7 = spw_w7 + c * 7;
                g = spw_g[c]; bb = spw_b[c]; mm = spw_m[c]; vv = spw_v[c]; off = 64;
            }

            float acc = src[l];
#pragma unroll
            for (int j = 0; j < 3; j++) {
                int idx = l + j - 1;
                if (idx >= 0 && idx < 64) acc += src[idx] * w3[j];
            }
#pragma unroll
            for (int j = 0; j < 7; j++) {
                int idx = l + j - 3;
                if (idx >= 0 && idx < 64) acc += src[idx] * w7[j];
            }
            acc *= (1.f / 3.f);
            const float scale = g * rsqrtf(vv + EPS);
            g_s[(size_t)bc * 128 + off + l] = (acc - mm) * scale + bb;
        }

        // All threads done reading tile[st] and csum/mrow/mcol for this slice.
        __syncthreads();

        // Refill the freed stage with slice i+2.
        if (i + 2 < SPC && tid == 0) {
            asm volatile("mbarrier.arrive.expect_tx.shared.b64 _, [%0], %1;"
                         :: "r"(mbar_a), "r"(16384u) : "memory");
            asm volatile(
                "cp.async.bulk.shared::cta.global.mbarrier::complete_tx::bytes "
                "[%0], [%1], %2, [%3];"
                :: "r"(st ? tile_a1 : tile_a0),
                   "l"(xbase + (size_t)(i + 2) * (NH * NW)),
                   "r"(16384u), "r"(mbar_a) : "memory");
        }
    }
}

// ---------------------------------------------------------------------------
// Kernel 2: conv1 (C->MIP) + BN1 + hswish -> g_y.  (R12 version)
// ---------------------------------------------------------------------------
__global__ __launch_bounds__(256) void k_y(
    const float* __restrict__ conv1_w,
    const float* __restrict__ bn1_g, const float* __restrict__ bn1_b,
    const float* __restrict__ bn1_m, const float* __restrict__ bn1_v)
{
    __shared__ float w1s[MIP * NC];        // 8 KB
    __shared__ float part[8][MIP * 32];    // 8 KB

    const int b   = blockIdx.x >> 2;
    const int lg  = blockIdx.x & 3;
    const int tid = threadIdx.x;
    const int cg  = tid >> 5;              // channel group 0..7
    const int l   = tid & 31;              // l within group

#pragma unroll
    for (int i = 0; i < MIP; i++) w1s[tid + i * NC] = conv1_w[tid + i * NC];
    __syncthreads();

    float acc[MIP];
#pragma unroll
    for (int m = 0; m < MIP; m++) acc[m] = 0.f;

    const float* sp = g_s + (size_t)b * NC * 128 + (size_t)(cg * 32) * 128 + lg * 32 + l;
#pragma unroll 8
    for (int cc = 0; cc < 32; cc++) {
        const float v = sp[cc * 128];
#pragma unroll
        for (int m = 0; m < MIP; m++) acc[m] += w1s[m * NC + cg * 32 + cc] * v;
    }
#pragma unroll
    for (int m = 0; m < MIP; m++) part[cg][m * 32 + l] = acc[m];
    __syncthreads();

    {
        float s = 0.f;
#pragma unroll
        for (int g = 0; g < 8; g++) s += part[g][tid];
        const int m = tid >> 5;
        const float scale = bn1_g[m] * rsqrtf(bn1_v[m] + EPS);
        const float val   = (s - bn1_m[m]) * scale + bn1_b[m];
        g_y[(size_t)b * (MIP * 128) + m * 128 + lg * 32 + (tid & 31)] =
            val * fminf(fmaxf(val + 3.f, 0.f), 6.f) * (1.f / 6.f);
    }
}

// ---------------------------------------------------------------------------
// Kernel 3 (fused): attention + stream via TMA. (R14 version — proven)
// ---------------------------------------------------------------------------
__global__ __launch_bounds__(256) void k_apply(
    const float* __restrict__ x,
    const float* __restrict__ convh_w, const float* __restrict__ convw_w,
    float* __restrict__ out)
{
    __shared__ __align__(128) float tile[NH * NW];   // 16 KB
    __shared__ unsigned long long mbar;
    __shared__ __align__(16) float ah[64];
    __shared__ __align__(16) float aw[64];

    const int bc  = (NB * NC - 1) - blockIdx.x;
    const int b   = bc >> 8;
    const int c   = bc & 255;
    const int tid = threadIdx.x;

    const uint32_t mbar_a = (uint32_t)__cvta_generic_to_shared(&mbar);
    const uint32_t tile_a = (uint32_t)__cvta_generic_to_shared(tile);

    if (tid == 0) {
        asm volatile("mbarrier.init.shared.b64 [%0], 1;" :: "r"(mbar_a) : "memory");
    }
    __syncthreads();
    if (tid == 0) {
        asm volatile("mbarrier.arrive.expect_tx.shared.b64 _, [%0], %1;"
                     :: "r"(mbar_a), "r"(16384u) : "memory");
        asm volatile(
            "cp.async.bulk.shared::cta.global.mbarrier::complete_tx::bytes "
            "[%0], [%1], %2, [%3];"
            :: "r"(tile_a), "l"(x + (size_t)bc * (NH * NW)), "r"(16384u), "r"(mbar_a)
            : "memory");
    }

    // Attention prologue overlaps the TMA flight (independent of x).
    if (tid < 128) {
        const int l   = tid & 63;
        const int off = (tid < 64) ? 0 : 64;
        const float* yb = g_y + (size_t)b * (MIP * 128) + off + l;
        const float* wp = ((tid < 64) ? convh_w : convw_w) + c * MIP;
        float s = 0.f;
#pragma unroll
        for (int m = 0; m < MIP; m++) s += wp[m] * __ldg(&yb[m * 128]);
        const float a = 1.f / (1.f + __expf(-s));
        ((tid < 64) ? ah : aw)[l] = a;
    }
    __syncthreads();

    {
        uint32_t done = 0;
        while (!done) {
            asm volatile(
                "{\n\t.reg .pred p;\n\t"
                "mbarrier.try_wait.parity.acquire.cta.shared::cta.b64 p, [%1], 0;\n\t"
                "selp.b32 %0, 1, 0, p;\n\t}"
                : "=r"(done) : "r"(mbar_a) : "memory");
        }
    }

    const float4* t4 = (const float4*)tile;
    float4*       o4 = (float4*)(out + (size_t)bc * (NH * NW));
#pragma unroll
    for (int i = 0; i < 4; i++) {
        const int f  = tid + i * 256;
        const int h  = f >> 4;
        const int w4 = f & 15;
        const float4 xv = t4[f];
        const float  a1 = ah[h];
        const float4 a2 = ((const float4*)aw)[w4];
        float4 o;
        o.x = xv.x * a1 * a2.x;
        o.y = xv.y * a1 * a2.y;
        o.z = xv.z * a1 * a2.z;
        o.w = xv.w * a1 * a2.w;
        __stcs(&o4[f], o);
    }
}

// ---------------------------------------------------------------------------
extern "C" void kernel_launch(void* const* d_in, const int* in_sizes, int n_in,
                              void* d_out, int out_size)
{
    const float* x       = (const float*)d_in[0];
    const float* sph_w3  = (const float*)d_in[1];
    const float* sph_w7  = (const float*)d_in[2];
    const float* sph_g   = (const float*)d_in[3];
    const float* sph_b   = (const float*)d_in[4];
    const float* sph_m   = (const float*)d_in[5];
    const float* sph_v   = (const float*)d_in[6];
    const float* spw_w3  = (const float*)d_in[7];
    const float* spw_w7  = (const float*)d_in[8];
    const float* spw_g   = (const float*)d_in[9];
    const float* spw_b   = (const float*)d_in[10];
    const float* spw_m   = (const float*)d_in[11];
    const float* spw_v   = (const float*)d_in[12];
    const float* conv1_w = (const float*)d_in[13];
    const float* bn1_g   = (const float*)d_in[14];
    const float* bn1_b   = (const float*)d_in[15];
    const float* bn1_m   = (const float*)d_in[16];
    const float* bn1_v   = (const float*)d_in[17];
    const float* convh_w = (const float*)d_in[18];
    const float* convw_w = (const float*)d_in[19];
    float* out = (float*)d_out;

    k_reduce_strip<<<NB * NC / SPC, 128>>>(x,
        sph_w3, sph_w7, sph_g, sph_b, sph_m, sph_v,
        spw_w3, spw_w7, spw_g, spw_b, spw_m, spw_v);

    k_y<<<NB * 4, 256>>>(conv1_w, bn1_g, bn1_b, bn1_m, bn1_v);

    k_apply<<<NB * NC, 256>>>(x, convh_w, convw_w, out);
}